// round 5
// baseline (speedup 1.0000x reference)
#include <cuda_runtime.h>
#include <cuda_bf16.h>
#include <math.h>
#include <stdint.h>

// ---------------- problem constants ----------------
#define N_ROWS 8192
#define F_IN   512
#define HID    256
#define WDIM   64

#define TMROWS 64
#define GRID_F (N_ROWS / TMROWS)   // 128 CTAs
#define NT     512
#define PNT    256

// weight pair counts (uint32 = 2 bf16 along K)
#define NW1P  (HID * (F_IN / 2))   // 65536
#define NW2P  (HID * (HID / 2))    // 32768
#define NWQP  (WDIM * (HID / 2))   // 8192
#define PREP_TOTAL (NW1P + NW2P + NWQP)
#define PREP_GRID  (PREP_TOTAL / PNT)

// ---------------- smem layout (uint32 units) ----------------
// A/E strides ≡ 4 (mod 32): conflict-free LDS.32 fragment reads
// B stride ≡ 8 (mod 32): conflict-free LDS.64 fragment reads (interleaved pairs)
#define LDA 36
#define LDB 40
#define LDE 132

#define U_EH   0                         // sEh [64*132] (sA tiles overlay this)
#define U_EL   8448                      // sEl
#define U_AH   0                         // sAh [64*36]
#define U_AL   2304                      // sAl
#define U_BH   16896                     // sBh [256*40]
#define U_BL   27136                     // sBl
#define U_QH   16896                     // sQh [64*132] (overlays sB)
#define U_QL   25344                     // sQl
#define U_C    37376                     // b1[256] b2[256] bq[64] wh[64]
#define SMEM_U32   38016
#define SMEM_BYTES (SMEM_U32 * 4)        // 152064

// ---------------- device globals ----------------
__device__ uint32_t g_W1Thi[NW1P];
__device__ uint32_t g_W1Tlo[NW1P];
__device__ uint32_t g_W2Thi[NW2P];
__device__ uint32_t g_W2Tlo[NW2P];
__device__ uint32_t g_WqThi[NWQP];
__device__ uint32_t g_WqTlo[NWQP];
__device__ float    g_partial[GRID_F];
__device__ unsigned g_count;

// ---------------- helpers ----------------
__device__ __forceinline__ void split2(float a, float b, uint32_t& hi, uint32_t& lo) {
    __nv_bfloat16 ha = __float2bfloat16(a), hb = __float2bfloat16(b);
    float ra = a - __bfloat162float(ha), rb = b - __bfloat162float(hb);
    __nv_bfloat16 la = __float2bfloat16(ra), lb = __float2bfloat16(rb);
    hi = (uint32_t)__bfloat16_as_ushort(ha) | ((uint32_t)__bfloat16_as_ushort(hb) << 16);
    lo = (uint32_t)__bfloat16_as_ushort(la) | ((uint32_t)__bfloat16_as_ushort(lb) << 16);
}

#define MMA_BF16(acc, a, b0, b1) \
    asm volatile("mma.sync.aligned.m16n8k16.row.col.f32.bf16.bf16.f32 " \
                 "{%0,%1,%2,%3}, {%4,%5,%6,%7}, {%8,%9}, {%0,%1,%2,%3};" \
                 : "+f"((acc)[0]), "+f"((acc)[1]), "+f"((acc)[2]), "+f"((acc)[3]) \
                 : "r"((a)[0]), "r"((a)[1]), "r"((a)[2]), "r"((a)[3]), \
                   "r"(b0), "r"(b1))

// ---------------- prep: weight split + transpose (K-major pairs) ----------------
__global__ void __launch_bounds__(PNT)
prep_kernel(const float* __restrict__ W1, const float* __restrict__ W2,
            const float* __restrict__ Wq)
{
    int p = blockIdx.x * PNT + threadIdx.x;
    if (p == 0) g_count = 0;
    if (p < NW1P) {
        int n = p >> 8, kk = (p & 255) * 2;
        split2(W1[kk * HID + n], W1[(kk + 1) * HID + n], g_W1Thi[p], g_W1Tlo[p]);
    } else if ((p -= NW1P) < NW2P) {
        int n = p >> 7, kk = (p & 127) * 2;
        split2(W2[kk * HID + n], W2[(kk + 1) * HID + n], g_W2Thi[p], g_W2Tlo[p]);
    } else if ((p -= NW2P) < NWQP) {
        int n = p >> 7, kk = (p & 127) * 2;
        split2(Wq[kk * WDIM + n], Wq[(kk + 1) * WDIM + n], g_WqThi[p], g_WqTlo[p]);
    }
}

// ---------------- main fused kernel ----------------
__global__ void __launch_bounds__(NT, 1)
main_kernel(const float* __restrict__ X,  const float* __restrict__ b1,
            const float* __restrict__ b2, const float* __restrict__ bq,
            const float* __restrict__ Wh, const float* __restrict__ bh,
            float* __restrict__ out)
{
    extern __shared__ uint32_t S[];
    uint32_t* sAh = S + U_AH; uint32_t* sAl = S + U_AL;
    uint32_t* sEh = S + U_EH; uint32_t* sEl = S + U_EL;
    uint32_t* sBh = S + U_BH; uint32_t* sBl = S + U_BL;
    uint32_t* sQh = S + U_QH; uint32_t* sQl = S + U_QL;
    float* sB1f = (float*)(S + U_C);
    float* sB2f = sB1f + 256;
    float* sBQf = sB2f + 256;
    float* sWHf = sBQf + 64;

    const int tid  = threadIdx.x;
    const int lane = tid & 31;
    const int warp = tid >> 5;
    const int wm   = warp & 3;          // M block (16 rows)
    const int wn   = warp >> 2;         // N block (64 cols L1/L2, 16 cols L3)
    const int g    = lane >> 2;
    const int kp   = lane & 3;
    const int row0 = blockIdx.x * TMROWS;
    const int arow = wm * 16 + g;

    // staging indices
    const int xr = tid >> 3, xc = tid & 7;      // X: 1 chunk of 8 floats / thread

    // consts
    if (tid < 256) { sB1f[tid] = b1[tid]; sB2f[tid] = b2[tid]; }
    else if (tid < 320) { sBQf[tid - 256] = bq[tid - 256]; sWHf[tid - 256] = Wh[tid - 256]; }

    float acc[8][4];
#pragma unroll
    for (int j = 0; j < 8; ++j)
#pragma unroll
        for (int q = 0; q < 4; ++q) acc[j][q] = 0.f;

    // prefetch registers
    float4 xv0, xv1;
    uint4 bhv[4], blv[4];

    // initial prefetch: X tile 0, W1 tile 0
    {
        const float4* xp = (const float4*)&X[(size_t)(row0 + xr) * F_IN + xc * 8];
        xv0 = xp[0]; xv1 = xp[1];
#pragma unroll
        for (int k = 0; k < 4; ++k) {
            int i = tid + k * NT, n = i >> 3, c = i & 7;
            bhv[k] = *(const uint4*)&g_W1Thi[n * 256 + c * 4];
            blv[k] = *(const uint4*)&g_W1Tlo[n * 256 + c * 4];
        }
    }

    // ========== Layer 1: X @ W1  (K=512, 8 tiles of 64) ==========
    for (int t = 0; t < 8; ++t) {
        __syncthreads();                 // prev tile fully consumed
        // store X tile (split fp32 -> bf16 hi/lo)
        {
            uint4 H, L;
            split2(xv0.x, xv0.y, H.x, L.x);
            split2(xv0.z, xv0.w, H.y, L.y);
            split2(xv1.x, xv1.y, H.z, L.z);
            split2(xv1.z, xv1.w, H.w, L.w);
            *(uint4*)&sAh[xr * LDA + xc * 4] = H;
            *(uint4*)&sAl[xr * LDA + xc * 4] = L;
        }
        // store B tile, interleaved: pair(k) and pair(k+8k?) -> adjacent
#pragma unroll
        for (int k = 0; k < 4; ++k) {
            int i = tid + k * NT, n = i >> 3, c = i & 7;
            int base = n * LDB + ((c >> 1) << 3) + (c & 1);
            sBh[base] = bhv[k].x; sBh[base + 2] = bhv[k].y;
            sBh[base + 4] = bhv[k].z; sBh[base + 6] = bhv[k].w;
            sBl[base] = blv[k].x; sBl[base + 2] = blv[k].y;
            sBl[base + 4] = blv[k].z; sBl[base + 6] = blv[k].w;
        }
        // prefetch next tile (overlaps the MMA loop below)
        if (t < 7) {
            const float4* xp = (const float4*)&X[(size_t)(row0 + xr) * F_IN + (t + 1) * 64 + xc * 8];
            xv0 = xp[0]; xv1 = xp[1];
#pragma unroll
            for (int k = 0; k < 4; ++k) {
                int i = tid + k * NT, n = i >> 3, c = i & 7;
                bhv[k] = *(const uint4*)&g_W1Thi[n * 256 + (t + 1) * 32 + c * 4];
                blv[k] = *(const uint4*)&g_W1Tlo[n * 256 + (t + 1) * 32 + c * 4];
            }
        }
        __syncthreads();
#pragma unroll
        for (int ks = 0; ks < 4; ++ks) {
            const int kb = ks * 8 + kp;
            uint32_t ah[4], al[4];
            ah[0] = sAh[arow * LDA + kb];      ah[1] = sAh[(arow + 8) * LDA + kb];
            ah[2] = sAh[arow * LDA + kb + 4];  ah[3] = sAh[(arow + 8) * LDA + kb + 4];
            al[0] = sAl[arow * LDA + kb];      al[1] = sAl[(arow + 8) * LDA + kb];
            al[2] = sAl[arow * LDA + kb + 4];  al[3] = sAl[(arow + 8) * LDA + kb + 4];
#pragma unroll
            for (int j = 0; j < 8; ++j) {
                int bi = (wn * 64 + j * 8 + g) * LDB + ks * 8 + kp * 2;
                uint2 bh = *(const uint2*)&sBh[bi];
                uint2 bl = *(const uint2*)&sBl[bi];
                MMA_BF16(acc[j], ah, bh.x, bh.y);
                MMA_BF16(acc[j], ah, bl.x, bl.y);
                MMA_BF16(acc[j], al, bh.x, bh.y);
            }
        }
    }

    // prefetch W2 tile 0 (regs free after last store)
#pragma unroll
    for (int k = 0; k < 4; ++k) {
        int i = tid + k * NT, n = i >> 3, c = i & 7;
        bhv[k] = *(const uint4*)&g_W2Thi[n * 128 + c * 4];
        blv[k] = *(const uint4*)&g_W2Tlo[n * 128 + c * 4];
    }
    __syncthreads();                      // L1 MMA reads done

    // epilogue 1: relu+bias, split -> sE (overlays sA)
#pragma unroll
    for (int j = 0; j < 8; ++j) {
        int n = wn * 64 + j * 8 + 2 * kp;
        float e0 = fmaxf(acc[j][0] + sB1f[n],     0.f);
        float e1 = fmaxf(acc[j][1] + sB1f[n + 1], 0.f);
        float e2 = fmaxf(acc[j][2] + sB1f[n],     0.f);
        float e3 = fmaxf(acc[j][3] + sB1f[n + 1], 0.f);
        int p0 = arow * LDE + (n >> 1), p1 = p0 + 8 * LDE;
        split2(e0, e1, sEh[p0], sEl[p0]);
        split2(e2, e3, sEh[p1], sEl[p1]);
        acc[j][0] = 0.f; acc[j][1] = 0.f; acc[j][2] = 0.f; acc[j][3] = 0.f;
    }
    // store W2 tile 0, prefetch tile 1
#pragma unroll
    for (int k = 0; k < 4; ++k) {
        int i = tid + k * NT, n = i >> 3, c = i & 7;
        int base = n * LDB + ((c >> 1) << 3) + (c & 1);
        sBh[base] = bhv[k].x; sBh[base + 2] = bhv[k].y;
        sBh[base + 4] = bhv[k].z; sBh[base + 6] = bhv[k].w;
        sBl[base] = blv[k].x; sBl[base + 2] = blv[k].y;
        sBl[base + 4] = blv[k].z; sBl[base + 6] = blv[k].w;
    }
#pragma unroll
    for (int k = 0; k < 4; ++k) {
        int i = tid + k * NT, n = i >> 3, c = i & 7;
        bhv[k] = *(const uint4*)&g_W2Thi[n * 128 + 32 + c * 4];
        blv[k] = *(const uint4*)&g_W2Tlo[n * 128 + 32 + c * 4];
    }
    __syncthreads();

    // ========== Layer 2: enc1 @ W2  (K=256, 4 tiles of 64) ==========
    for (int t = 0; t < 4; ++t) {
#pragma unroll
        for (int ks = 0; ks < 4; ++ks) {
            const int kb  = ks * 8 + kp;
            const int kbE = t * 32 + kb;
            uint32_t ah[4], al[4];
            ah[0] = sEh[arow * LDE + kbE];      ah[1] = sEh[(arow + 8) * LDE + kbE];
            ah[2] = sEh[arow * LDE + kbE + 4];  ah[3] = sEh[(arow + 8) * LDE + kbE + 4];
            al[0] = sEl[arow * LDE + kbE];      al[1] = sEl[(arow + 8) * LDE + kbE];
            al[2] = sEl[arow * LDE + kbE + 4];  al[3] = sEl[(arow + 8) * LDE + kbE + 4];
#pragma unroll
            for (int j = 0; j < 8; ++j) {
                int bi = (wn * 64 + j * 8 + g) * LDB + ks * 8 + kp * 2;
                uint2 bh = *(const uint2*)&sBh[bi];
                uint2 bl = *(const uint2*)&sBl[bi];
                MMA_BF16(acc[j], ah, bh.x, bh.y);
                MMA_BF16(acc[j], ah, bl.x, bl.y);
                MMA_BF16(acc[j], al, bh.x, bh.y);
            }
        }
        __syncthreads();                  // B tile consumed
        if (t < 3) {
            // store next tile (regs hold t+1)
#pragma unroll
            for (int k = 0; k < 4; ++k) {
                int i = tid + k * NT, n = i >> 3, c = i & 7;
                int base = n * LDB + ((c >> 1) << 3) + (c & 1);
                sBh[base] = bhv[k].x; sBh[base + 2] = bhv[k].y;
                sBh[base + 4] = bhv[k].z; sBh[base + 6] = bhv[k].w;
                sBl[base] = blv[k].x; sBl[base + 2] = blv[k].y;
                sBl[base + 4] = blv[k].z; sBl[base + 6] = blv[k].w;
            }
            if (t < 2) {                  // prefetch W2 tile t+2
#pragma unroll
                for (int k = 0; k < 4; ++k) {
                    int i = tid + k * NT, n = i >> 3, c = i & 7;
                    bhv[k] = *(const uint4*)&g_W2Thi[n * 128 + (t + 2) * 32 + c * 4];
                    blv[k] = *(const uint4*)&g_W2Tlo[n * 128 + (t + 2) * 32 + c * 4];
                }
            } else {                      // t==2: prefetch Wq (full)
#pragma unroll
                for (int k = 0; k < 4; ++k) {
                    int i = tid + k * NT, n = i >> 5, c = i & 31;
                    bhv[k] = *(const uint4*)&g_WqThi[n * 128 + c * 4];
                    blv[k] = *(const uint4*)&g_WqTlo[n * 128 + c * 4];
                }
            }
            __syncthreads();
        }
    }

    // epilogue 2: relu+bias -> sE in place; store Wq -> sQ (overlays sB)
#pragma unroll
    for (int j = 0; j < 8; ++j) {
        int n = wn * 64 + j * 8 + 2 * kp;
        float e0 = fmaxf(acc[j][0] + sB2f[n],     0.f);
        float e1 = fmaxf(acc[j][1] + sB2f[n + 1], 0.f);
        float e2 = fmaxf(acc[j][2] + sB2f[n],     0.f);
        float e3 = fmaxf(acc[j][3] + sB2f[n + 1], 0.f);
        int p0 = arow * LDE + (n >> 1), p1 = p0 + 8 * LDE;
        split2(e0, e1, sEh[p0], sEl[p0]);
        split2(e2, e3, sEh[p1], sEl[p1]);
    }
#pragma unroll
    for (int k = 0; k < 4; ++k) {
        int i = tid + k * NT, n = i >> 5, c = i & 31;
        *(uint4*)&sQh[n * LDE + c * 4] = bhv[k];
        *(uint4*)&sQl[n * LDE + c * 4] = blv[k];
    }
    __syncthreads();

    // ========== Layer 3: enc2 @ Wq  (K=256, N=64) ==========
    float acc3[2][4];
#pragma unroll
    for (int j = 0; j < 2; ++j)
#pragma unroll
        for (int q = 0; q < 4; ++q) acc3[j][q] = 0.f;

#pragma unroll
    for (int ks = 0; ks < 16; ++ks) {
        const int kb = ks * 8 + kp;
        uint32_t ah[4], al[4];
        ah[0] = sEh[arow * LDE + kb];      ah[1] = sEh[(arow + 8) * LDE + kb];
        ah[2] = sEh[arow * LDE + kb + 4];  ah[3] = sEh[(arow + 8) * LDE + kb + 4];
        al[0] = sEl[arow * LDE + kb];      al[1] = sEl[(arow + 8) * LDE + kb];
        al[2] = sEl[arow * LDE + kb + 4];  al[3] = sEl[(arow + 8) * LDE + kb + 4];
#pragma unroll
        for (int j = 0; j < 2; ++j) {
            int bi = (wn * 16 + j * 8 + g) * LDE + kb;
            uint32_t bh0 = sQh[bi], bh1 = sQh[bi + 4];
            uint32_t bl0 = sQl[bi], bl1 = sQl[bi + 4];
            MMA_BF16(acc3[j], ah, bh0, bh1);
            MMA_BF16(acc3[j], ah, bl0, bl1);
            MMA_BF16(acc3[j], al, bh0, bh1);
        }
    }

    // final: q = tanh(pre + bq); partial = sum q * Wh
    float part = 0.f;
#pragma unroll
    for (int j = 0; j < 2; ++j) {
        int n = wn * 16 + j * 8 + 2 * kp;
        part = fmaf(tanhf(acc3[j][0] + sBQf[n]),     sWHf[n],     part);
        part = fmaf(tanhf(acc3[j][1] + sBQf[n + 1]), sWHf[n + 1], part);
        part = fmaf(tanhf(acc3[j][2] + sBQf[n]),     sWHf[n],     part);
        part = fmaf(tanhf(acc3[j][3] + sBQf[n + 1]), sWHf[n + 1], part);
    }

    __syncthreads();
    float* red = (float*)S;
    red[tid] = part;
    __syncthreads();
    for (int s = NT / 2; s > 0; s >>= 1) {
        if (tid < s) red[tid] += red[tid + s];
        __syncthreads();
    }

    __shared__ int s_last;
    if (tid == 0) {
        g_partial[blockIdx.x] = red[0];
        __threadfence();
        unsigned v = atomicAdd(&g_count, 1u);
        s_last = (v == GRID_F - 1) ? 1 : 0;
    }
    __syncthreads();
    if (s_last) {
        if (tid < GRID_F)
            red[tid] = ((const volatile float*)g_partial)[tid];
        __syncthreads();
        for (int s = GRID_F / 2; s > 0; s >>= 1) {
            if (tid < s) red[tid] += red[tid + s];
            __syncthreads();
        }
        if (tid == 0) out[0] = red[0] + bh[0];
    }
}

extern "C" void kernel_launch(void* const* d_in, const int* in_sizes, int n_in,
                              void* d_out, int out_size)
{
    const float* X  = (const float*)d_in[0];
    const float* W1 = (const float*)d_in[1];
    const float* b1 = (const float*)d_in[2];
    const float* W2 = (const float*)d_in[3];
    const float* b2 = (const float*)d_in[4];
    const float* Wq = (const float*)d_in[5];
    const float* bq = (const float*)d_in[6];
    const float* Wh = (const float*)d_in[7];
    const float* bh = (const float*)d_in[8];
    float* out = (float*)d_out;

    cudaFuncSetAttribute(main_kernel,
                         cudaFuncAttributeMaxDynamicSharedMemorySize, SMEM_BYTES);

    prep_kernel<<<PREP_GRID, PNT>>>(W1, W2, Wq);
    main_kernel<<<GRID_F, NT, SMEM_BYTES>>>(X, b1, b2, bq, Wh, bh, out);
}

// round 6
// speedup vs baseline: 1.2484x; 1.2484x over previous
#include <cuda_runtime.h>
#include <cuda_bf16.h>
#include <math.h>
#include <stdint.h>

// ---------------- problem constants ----------------
#define N_ROWS 8192
#define F_IN   512
#define HID    256
#define WDIM   64

#define TMROWS 64
#define GRID_F 128
#define NT     512
#define PNT    256

// gmem weight sizes (u32 bf16-pairs)
#define NW1P  65536       // 32 K-chunks x 256 n x 8 (interleaved)
#define NW2P  32768       // 16 K-chunks x 256 x 8
#define NWQP  8192        // 64 n x 128 pairs (plain)
#define PREP_TOTAL (NW1P + NW2P + NWQP)
#define PREP_GRID  (PREP_TOTAL / PNT)

// ---------------- smem layout (u32 units) ----------------
#define LDA 20            // A tile stride (16 pairs + 4 pad), ≡4 mod 32
#define LDE 132           // enc / Wq stride (128 pairs + 4), ≡4 mod 32

#define U_A0H 0           // A double buffers (overlay E region temporally)
#define U_A0L 1280
#define U_A1H 2560
#define U_A1L 3840
#define U_E   0           // sEh [64*132] = 8448
#define U_EL  8448        // sEl
#define U_B   16896       // B bufs: buf c @ U_B + c*8192 (hi 4096 | lo 4096); Wq reuses (needs 16896)
#define U_C   33792       // consts: b1[256] b2[256] bq[64] wh[64]
#define SMEM_U32   34432
#define SMEM_BYTES (SMEM_U32 * 4)   // 137728

// ---------------- device globals ----------------
__device__ uint32_t g_W1Thi[NW1P];
__device__ uint32_t g_W1Tlo[NW1P];
__device__ uint32_t g_W2Thi[NW2P];
__device__ uint32_t g_W2Tlo[NW2P];
__device__ uint32_t g_WqThi[NWQP];
__device__ uint32_t g_WqTlo[NWQP];
__device__ float    g_partial[GRID_F];
__device__ unsigned g_count;

// ---------------- helpers ----------------
__device__ __forceinline__ void split2(float a, float b, uint32_t& hi, uint32_t& lo) {
    __nv_bfloat16 ha = __float2bfloat16(a), hb = __float2bfloat16(b);
    float ra = a - __bfloat162float(ha), rb = b - __bfloat162float(hb);
    __nv_bfloat16 la = __float2bfloat16(ra), lb = __float2bfloat16(rb);
    hi = (uint32_t)__bfloat16_as_ushort(ha) | ((uint32_t)__bfloat16_as_ushort(hb) << 16);
    lo = (uint32_t)__bfloat16_as_ushort(la) | ((uint32_t)__bfloat16_as_ushort(lb) << 16);
}

#define MMA_BF16(acc, a, b0, b1) \
    asm volatile("mma.sync.aligned.m16n8k16.row.col.f32.bf16.bf16.f32 " \
                 "{%0,%1,%2,%3}, {%4,%5,%6,%7}, {%8,%9}, {%0,%1,%2,%3};" \
                 : "+f"((acc)[0]), "+f"((acc)[1]), "+f"((acc)[2]), "+f"((acc)[3]) \
                 : "r"((a)[0]), "r"((a)[1]), "r"((a)[2]), "r"((a)[3]), \
                   "r"(b0), "r"(b1))

#define CP16(sm_bytes, gptr) \
    asm volatile("cp.async.cg.shared.global [%0], [%1], 16;" \
                 :: "r"(sm_bytes), "l"(gptr))
#define CP_COMMIT() asm volatile("cp.async.commit_group;")
#define CP_WAIT0()  asm volatile("cp.async.wait_group 0;" ::: "memory")
#define CP_WAIT1()  asm volatile("cp.async.wait_group 1;" ::: "memory")

// ---------------- prep: weight split + transpose + pair-interleave ----------------
// W1/W2 layout: idx = (c2*256 + n)*8 + q, c2 = K-chunk of 8 pairs,
// q = interleaved position: pair p -> q = 2*(p&3) + (p>>2)  (inverse p = 4*(q&1) + (q>>1))
__global__ void __launch_bounds__(PNT)
prep_kernel(const float* __restrict__ W1, const float* __restrict__ W2,
            const float* __restrict__ Wq)
{
    int p = blockIdx.x * PNT + threadIdx.x;
    if (p == 0) g_count = 0;
    if (p < NW1P) {
        int q = p & 7, n = (p >> 3) & 255, c2 = p >> 11;
        int pp = ((q & 1) << 2) | (q >> 1);
        int kk = (c2 * 8 + pp) * 2;
        split2(W1[kk * HID + n], W1[(kk + 1) * HID + n], g_W1Thi[p], g_W1Tlo[p]);
    } else if ((p -= NW1P) < NW2P) {
        int q = p & 7, n = (p >> 3) & 255, c2 = p >> 11;
        int pp = ((q & 1) << 2) | (q >> 1);
        int kk = (c2 * 8 + pp) * 2;
        split2(W2[kk * HID + n], W2[(kk + 1) * HID + n], g_W2Thi[p], g_W2Tlo[p]);
    } else if ((p -= NW2P) < NWQP) {
        int n = p >> 7, kk = (p & 127) * 2;
        split2(Wq[kk * WDIM + n], Wq[(kk + 1) * WDIM + n], g_WqThi[p], g_WqTlo[p]);
    }
}

// ---------------- main fused kernel ----------------
__global__ void __launch_bounds__(NT, 1)
main_kernel(const float* __restrict__ X,  const float* __restrict__ b1,
            const float* __restrict__ b2, const float* __restrict__ bq,
            const float* __restrict__ Wh, const float* __restrict__ bh,
            float* __restrict__ out)
{
    extern __shared__ uint32_t S[];
    const unsigned sb4 = (unsigned)__cvta_generic_to_shared(S);

    float* sB1f = (float*)(S + U_C);
    float* sB2f = sB1f + 256;
    float* sBQf = sB2f + 256;
    float* sWHf = sBQf + 64;

    const int tid  = threadIdx.x;
    const int lane = tid & 31;
    const int warp = tid >> 5;
    const int wm   = warp & 3;          // 4 M blocks of 16 rows
    const int wn   = warp >> 2;         // 4 N blocks (64 cols L1/L2, 16 cols L3)
    const int g    = lane >> 2;
    const int kp   = lane & 3;
    const int row0 = blockIdx.x * TMROWS;
    const int arow = wm * 16 + g;

    const int xr = tid >> 3, xc = tid & 7;   // X stage: 1 float4 / thread / tile

    if (tid < 256) { sB1f[tid] = b1[tid]; sB2f[tid] = b2[tid]; }
    else if (tid < 320) { sBQf[tid - 256] = bq[tid - 256]; sWHf[tid - 256] = Wh[tid - 256]; }

    float acc[8][4];
#pragma unroll
    for (int j = 0; j < 8; ++j)
#pragma unroll
        for (int q = 0; q < 4; ++q) acc[j][q] = 0.f;

    const float* xrow = X + (size_t)(row0 + xr) * F_IN + xc * 4;

    // prologue: X tile0 -> regs ; B(W1) tile0 -> buf0 via cp.async
    float4 xv = *(const float4*)xrow;
#pragma unroll
    for (int k = 0; k < 2; ++k) {
        int i = (tid + k * NT) * 4;                       // u32 offset, contiguous copy
        CP16(sb4 + (U_B + i) * 4,        g_W1Thi + i);
        CP16(sb4 + (U_B + 4096 + i) * 4, g_W1Tlo + i);
    }
    CP_COMMIT();

    // ========== Layer 1: X @ W1  (16 K-tiles of 32) ==========
#pragma unroll 2
    for (int t = 0; t < 16; ++t) {
        const int cur = t & 1;
        const int abH = cur ? U_A1H : U_A0H;
        const int abL = cur ? U_A1L : U_A0L;
        const int bb  = U_B + cur * 8192;
        // store A tile (split fp32 -> bf16 hi/lo pairs)
        {
            uint2 H, L;
            split2(xv.x, xv.y, H.x, L.x);
            split2(xv.z, xv.w, H.y, L.y);
            *(uint2*)&S[abH + xr * LDA + xc * 2] = H;
            *(uint2*)&S[abL + xr * LDA + xc * 2] = L;
        }
        if (t < 15) {
            xv = *(const float4*)(xrow + (t + 1) * 32);
            const int nb = U_B + (1 - cur) * 8192;
#pragma unroll
            for (int k = 0; k < 2; ++k) {
                int i = (tid + k * NT) * 4;
                CP16(sb4 + (nb + i) * 4,        g_W1Thi + (t + 1) * 4096 + i);
                CP16(sb4 + (nb + 4096 + i) * 4, g_W1Tlo + (t + 1) * 4096 + i);
            }
            CP_COMMIT();
            CP_WAIT1();
        } else {
            CP_WAIT0();
        }
        __syncthreads();
#pragma unroll
        for (int ks = 0; ks < 2; ++ks) {
            const int kb = ks * 8 + kp;
            uint32_t ah[4], al[4];
            ah[0] = S[abH + arow * LDA + kb];      ah[1] = S[abH + (arow + 8) * LDA + kb];
            ah[2] = S[abH + arow * LDA + kb + 4];  ah[3] = S[abH + (arow + 8) * LDA + kb + 4];
            al[0] = S[abL + arow * LDA + kb];      al[1] = S[abL + (arow + 8) * LDA + kb];
            al[2] = S[abL + arow * LDA + kb + 4];  al[3] = S[abL + (arow + 8) * LDA + kb + 4];
#pragma unroll
            for (int j = 0; j < 8; ++j) {
                int bi = bb + ks * 2048 + (wn * 64 + j * 8 + g) * 8 + 2 * kp;
                uint2 bhv = *(const uint2*)&S[bi];
                uint2 blv = *(const uint2*)&S[bi + 4096];
                MMA_BF16(acc[j], ah, bhv.x, bhv.y);
                MMA_BF16(acc[j], ah, blv.x, blv.y);
                MMA_BF16(acc[j], al, bhv.x, bhv.y);
            }
        }
        __syncthreads();
    }

    // prefetch W2 tile0 -> buf0 (B buffers idle now)
#pragma unroll
    for (int k = 0; k < 2; ++k) {
        int i = (tid + k * NT) * 4;
        CP16(sb4 + (U_B + i) * 4,        g_W2Thi + i);
        CP16(sb4 + (U_B + 4096 + i) * 4, g_W2Tlo + i);
    }
    CP_COMMIT();

    // epilogue 1: relu+bias, split -> sE (overlays dead A bufs; overlaps the copy)
#pragma unroll
    for (int j = 0; j < 8; ++j) {
        int n = wn * 64 + j * 8 + 2 * kp;
        float e0 = fmaxf(acc[j][0] + sB1f[n],     0.f);
        float e1 = fmaxf(acc[j][1] + sB1f[n + 1], 0.f);
        float e2 = fmaxf(acc[j][2] + sB1f[n],     0.f);
        float e3 = fmaxf(acc[j][3] + sB1f[n + 1], 0.f);
        int p0 = arow * LDE + (n >> 1), p1 = p0 + 8 * LDE;
        split2(e0, e1, S[U_E + p0],  S[U_EL + p0]);
        split2(e2, e3, S[U_E + p1],  S[U_EL + p1]);
        acc[j][0] = 0.f; acc[j][1] = 0.f; acc[j][2] = 0.f; acc[j][3] = 0.f;
    }

    // ========== Layer 2: enc1 @ W2  (8 K-tiles of 32) ==========
#pragma unroll 2
    for (int t = 0; t < 8; ++t) {
        const int cur = t & 1;
        const int bb  = U_B + cur * 8192;
        if (t < 7) {
            const int nb = U_B + (1 - cur) * 8192;
#pragma unroll
            for (int k = 0; k < 2; ++k) {
                int i = (tid + k * NT) * 4;
                CP16(sb4 + (nb + i) * 4,        g_W2Thi + (t + 1) * 4096 + i);
                CP16(sb4 + (nb + 4096 + i) * 4, g_W2Tlo + (t + 1) * 4096 + i);
            }
            CP_COMMIT();
            CP_WAIT1();
        } else {
            CP_WAIT0();
        }
        __syncthreads();
#pragma unroll
        for (int ks = 0; ks < 2; ++ks) {
            const int kb  = ks * 8 + kp;
            const int kbE = t * 16 + kb;
            uint32_t ah[4], al[4];
            ah[0] = S[U_E + arow * LDE + kbE];       ah[1] = S[U_E + (arow + 8) * LDE + kbE];
            ah[2] = S[U_E + arow * LDE + kbE + 4];   ah[3] = S[U_E + (arow + 8) * LDE + kbE + 4];
            al[0] = S[U_EL + arow * LDE + kbE];      al[1] = S[U_EL + (arow + 8) * LDE + kbE];
            al[2] = S[U_EL + arow * LDE + kbE + 4];  al[3] = S[U_EL + (arow + 8) * LDE + kbE + 4];
#pragma unroll
            for (int j = 0; j < 8; ++j) {
                int bi = bb + ks * 2048 + (wn * 64 + j * 8 + g) * 8 + 2 * kp;
                uint2 bhv = *(const uint2*)&S[bi];
                uint2 blv = *(const uint2*)&S[bi + 4096];
                MMA_BF16(acc[j], ah, bhv.x, bhv.y);
                MMA_BF16(acc[j], ah, blv.x, blv.y);
                MMA_BF16(acc[j], al, bhv.x, bhv.y);
            }
        }
        __syncthreads();
    }

    // stage Wq -> U_B region (cp.async), overlap with epilogue 2
#pragma unroll
    for (int k = 0; k < 8; ++k) {
        int i = tid + k * NT;
        int comp = i >> 11, r = i & 2047;
        int n = r >> 5, c = r & 31;
        const uint32_t* gp = comp ? g_WqTlo : g_WqThi;
        CP16(sb4 + (U_B + comp * 8448 + n * LDE + c * 4) * 4, gp + n * 128 + c * 4);
    }
    CP_COMMIT();

    // epilogue 2: relu+bias -> sE in place
#pragma unroll
    for (int j = 0; j < 8; ++j) {
        int n = wn * 64 + j * 8 + 2 * kp;
        float e0 = fmaxf(acc[j][0] + sB2f[n],     0.f);
        float e1 = fmaxf(acc[j][1] + sB2f[n + 1], 0.f);
        float e2 = fmaxf(acc[j][2] + sB2f[n],     0.f);
        float e3 = fmaxf(acc[j][3] + sB2f[n + 1], 0.f);
        int p0 = arow * LDE + (n >> 1), p1 = p0 + 8 * LDE;
        split2(e0, e1, S[U_E + p0],  S[U_EL + p0]);
        split2(e2, e3, S[U_E + p1],  S[U_EL + p1]);
    }
    CP_WAIT0();
    __syncthreads();

    // ========== Layer 3: enc2 @ Wq  (K=256, N=64) ==========
    float acc3[2][4];
#pragma unroll
    for (int j = 0; j < 2; ++j)
#pragma unroll
        for (int q = 0; q < 4; ++q) acc3[j][q] = 0.f;

#pragma unroll
    for (int ks = 0; ks < 16; ++ks) {
        const int kb = ks * 8 + kp;
        uint32_t ah[4], al[4];
        ah[0] = S[U_E + arow * LDE + kb];       ah[1] = S[U_E + (arow + 8) * LDE + kb];
        ah[2] = S[U_E + arow * LDE + kb + 4];   ah[3] = S[U_E + (arow + 8) * LDE + kb + 4];
        al[0] = S[U_EL + arow * LDE + kb];      al[1] = S[U_EL + (arow + 8) * LDE + kb];
        al[2] = S[U_EL + arow * LDE + kb + 4];  al[3] = S[U_EL + (arow + 8) * LDE + kb + 4];
#pragma unroll
        for (int j = 0; j < 2; ++j) {
            int bi = U_B + (wn * 16 + j * 8 + g) * LDE + kb;
            uint32_t bh0 = S[bi],        bh1 = S[bi + 4];
            uint32_t bl0 = S[bi + 8448], bl1 = S[bi + 8448 + 4];
            MMA_BF16(acc3[j], ah, bh0, bh1);
            MMA_BF16(acc3[j], ah, bl0, bl1);
            MMA_BF16(acc3[j], al, bh0, bh1);
        }
    }

    // final: q = tanh(pre + bq); partial = sum q * Wh
    float part = 0.f;
#pragma unroll
    for (int j = 0; j < 2; ++j) {
        int n = wn * 16 + j * 8 + 2 * kp;
        part = fmaf(tanhf(acc3[j][0] + sBQf[n]),     sWHf[n],     part);
        part = fmaf(tanhf(acc3[j][1] + sBQf[n + 1]), sWHf[n + 1], part);
        part = fmaf(tanhf(acc3[j][2] + sBQf[n]),     sWHf[n],     part);
        part = fmaf(tanhf(acc3[j][3] + sBQf[n + 1]), sWHf[n + 1], part);
    }

    __syncthreads();
    float* red = (float*)S;
    red[tid] = part;
    __syncthreads();
    for (int s = NT / 2; s > 0; s >>= 1) {
        if (tid < s) red[tid] += red[tid + s];
        __syncthreads();
    }

    __shared__ int s_last;
    if (tid == 0) {
        g_partial[blockIdx.x] = red[0];
        __threadfence();
        unsigned v = atomicAdd(&g_count, 1u);
        s_last = (v == GRID_F - 1) ? 1 : 0;
    }
    __syncthreads();
    if (s_last) {
        if (tid < GRID_F)
            red[tid] = ((const volatile float*)g_partial)[tid];
        __syncthreads();
        for (int s = GRID_F / 2; s > 0; s >>= 1) {
            if (tid < s) red[tid] += red[tid + s];
            __syncthreads();
        }
        if (tid == 0) out[0] = red[0] + bh[0];
    }
}

extern "C" void kernel_launch(void* const* d_in, const int* in_sizes, int n_in,
                              void* d_out, int out_size)
{
    const float* X  = (const float*)d_in[0];
    const float* W1 = (const float*)d_in[1];
    const float* b1 = (const float*)d_in[2];
    const float* W2 = (const float*)d_in[3];
    const float* b2 = (const float*)d_in[4];
    const float* Wq = (const float*)d_in[5];
    const float* bq = (const float*)d_in[6];
    const float* Wh = (const float*)d_in[7];
    const float* bh = (const float*)d_in[8];
    float* out = (float*)d_out;

    cudaFuncSetAttribute(main_kernel,
                         cudaFuncAttributeMaxDynamicSharedMemorySize, SMEM_BYTES);

    prep_kernel<<<PREP_GRID, PNT>>>(W1, W2, Wq);
    main_kernel<<<GRID_F, NT, SMEM_BYTES>>>(X, b1, b2, bq, Wh, bh, out);
}